// round 1
// baseline (speedup 1.0000x reference)
#include <cuda_runtime.h>
#include <math.h>
#include <stdint.h>

// Problem dims
#define BATCH   65536
#define EDIM    512
#define NH      8
#define DH      64
#define ROWS2   (2*BATCH)      // 131072 sequence rows
#define QKVN    1536
#define CONCATD 1024
#define HIDD    512
#define OUTD    256

// ---------------- scratch (no allocations allowed) ----------------
__device__ float g_qkv[(size_t)ROWS2 * QKVN];   // 2B x 1536
__device__ float g_ctx[(size_t)ROWS2 * EDIM];   // 2B x 512
__device__ float g_att[(size_t)ROWS2 * EDIM];   // 2B x 512  (== B x 1024 view)
__device__ float g_h  [(size_t)BATCH * HIDD];   // B x 512
__device__ float g_o  [(size_t)BATCH * OUTD];   // B x 256

// ---------------- SGEMM: C(MxN) = A(MxK) @ W(NxK)^T + bias, optional GELU ----
// BM=BN=128, BK=16, 256 threads, 8x8 micro-tile per thread.
template <int EPI>  // 0 = none, 1 = gelu(exact erf)
__global__ __launch_bounds__(256)
void sgemm_nt(const float* __restrict__ A, const float* __restrict__ W,
              const float* __restrict__ bias, float* __restrict__ C,
              int M, int N, int K) {
    constexpr int BM = 128, BN = 128, BK = 16;
    __shared__ float As[BK][BM];
    __shared__ float Bs[BK][BN];

    const int tid = threadIdx.x;
    const int m0 = blockIdx.y * BM;
    const int n0 = blockIdx.x * BN;
    const int tx = tid & 15;       // 0..15 -> n micro
    const int ty = tid >> 4;       // 0..15 -> m micro
    const int lRow = tid >> 2;     // 0..63
    const int lCol = (tid & 3) * 4;

    float acc[8][8];
#pragma unroll
    for (int i = 0; i < 8; i++)
#pragma unroll
        for (int j = 0; j < 8; j++) acc[i][j] = 0.f;

    for (int k0 = 0; k0 < K; k0 += BK) {
#pragma unroll
        for (int it = 0; it < 2; ++it) {
            int row = lRow + it * 64;
            float4 a = *(const float4*)(A + (size_t)(m0 + row) * K + k0 + lCol);
            As[lCol + 0][row] = a.x; As[lCol + 1][row] = a.y;
            As[lCol + 2][row] = a.z; As[lCol + 3][row] = a.w;
            float4 b = *(const float4*)(W + (size_t)(n0 + row) * K + k0 + lCol);
            Bs[lCol + 0][row] = b.x; Bs[lCol + 1][row] = b.y;
            Bs[lCol + 2][row] = b.z; Bs[lCol + 3][row] = b.w;
        }
        __syncthreads();
#pragma unroll
        for (int kk = 0; kk < BK; ++kk) {
            float4 a0 = *(const float4*)&As[kk][ty * 8];
            float4 a1 = *(const float4*)&As[kk][ty * 8 + 4];
            float4 b0 = *(const float4*)&Bs[kk][tx * 8];
            float4 b1 = *(const float4*)&Bs[kk][tx * 8 + 4];
            float av[8] = {a0.x, a0.y, a0.z, a0.w, a1.x, a1.y, a1.z, a1.w};
            float bv[8] = {b0.x, b0.y, b0.z, b0.w, b1.x, b1.y, b1.z, b1.w};
#pragma unroll
            for (int i = 0; i < 8; i++)
#pragma unroll
                for (int j = 0; j < 8; j++) acc[i][j] += av[i] * bv[j];
        }
        __syncthreads();
    }

#pragma unroll
    for (int i = 0; i < 8; i++) {
        size_t m = (size_t)(m0 + ty * 8 + i);
#pragma unroll
        for (int j = 0; j < 8; j += 4) {
            int n = n0 + tx * 8 + j;
            float4 v;
            v.x = acc[i][j + 0] + bias[n + 0];
            v.y = acc[i][j + 1] + bias[n + 1];
            v.z = acc[i][j + 2] + bias[n + 2];
            v.w = acc[i][j + 3] + bias[n + 3];
            if (EPI == 1) {
                v.x = 0.5f * v.x * (1.0f + erff(v.x * 0.70710678118654752f));
                v.y = 0.5f * v.y * (1.0f + erff(v.y * 0.70710678118654752f));
                v.z = 0.5f * v.z * (1.0f + erff(v.z * 0.70710678118654752f));
                v.w = 0.5f * v.w * (1.0f + erff(v.w * 0.70710678118654752f));
            }
            *(float4*)(C + m * N + n) = v;
        }
    }
}

// ---------------- QKV GEMM: A rows interleave visual/text ----------------
__global__ __launch_bounds__(256)
void sgemm_qkv(const float* __restrict__ vis, const float* __restrict__ txt,
               const float* __restrict__ W, const float* __restrict__ bias,
               float* __restrict__ C) {
    constexpr int BM = 128, BN = 128, BK = 16;
    const int K = EDIM, N = QKVN;
    __shared__ float As[BK][BM];
    __shared__ float Bs[BK][BN];

    const int tid = threadIdx.x;
    const int m0 = blockIdx.y * BM;
    const int n0 = blockIdx.x * BN;
    const int tx = tid & 15;
    const int ty = tid >> 4;
    const int lRow = tid >> 2;
    const int lCol = (tid & 3) * 4;

    float acc[8][8];
#pragma unroll
    for (int i = 0; i < 8; i++)
#pragma unroll
        for (int j = 0; j < 8; j++) acc[i][j] = 0.f;

    for (int k0 = 0; k0 < K; k0 += BK) {
#pragma unroll
        for (int it = 0; it < 2; ++it) {
            int row = lRow + it * 64;
            int grow = m0 + row;
            const float* src = (grow & 1) ? txt : vis;
            float4 a = *(const float4*)(src + (size_t)(grow >> 1) * EDIM + k0 + lCol);
            As[lCol + 0][row] = a.x; As[lCol + 1][row] = a.y;
            As[lCol + 2][row] = a.z; As[lCol + 3][row] = a.w;
            float4 b = *(const float4*)(W + (size_t)(n0 + row) * K + k0 + lCol);
            Bs[lCol + 0][row] = b.x; Bs[lCol + 1][row] = b.y;
            Bs[lCol + 2][row] = b.z; Bs[lCol + 3][row] = b.w;
        }
        __syncthreads();
#pragma unroll
        for (int kk = 0; kk < BK; ++kk) {
            float4 a0 = *(const float4*)&As[kk][ty * 8];
            float4 a1 = *(const float4*)&As[kk][ty * 8 + 4];
            float4 b0 = *(const float4*)&Bs[kk][tx * 8];
            float4 b1 = *(const float4*)&Bs[kk][tx * 8 + 4];
            float av[8] = {a0.x, a0.y, a0.z, a0.w, a1.x, a1.y, a1.z, a1.w};
            float bv[8] = {b0.x, b0.y, b0.z, b0.w, b1.x, b1.y, b1.z, b1.w};
#pragma unroll
            for (int i = 0; i < 8; i++)
#pragma unroll
                for (int j = 0; j < 8; j++) acc[i][j] += av[i] * bv[j];
        }
        __syncthreads();
    }

#pragma unroll
    for (int i = 0; i < 8; i++) {
        size_t m = (size_t)(m0 + ty * 8 + i);
#pragma unroll
        for (int j = 0; j < 8; j += 4) {
            int n = n0 + tx * 8 + j;
            float4 v;
            v.x = acc[i][j + 0] + bias[n + 0];
            v.y = acc[i][j + 1] + bias[n + 1];
            v.z = acc[i][j + 2] + bias[n + 2];
            v.w = acc[i][j + 3] + bias[n + 3];
            *(float4*)(C + m * N + n) = v;
        }
    }
}

// ---------------- attention: one thread per (b, h); seq len 2 ----------------
__device__ __forceinline__ float dot4(float4 a, float4 b) {
    return a.x * b.x + a.y * b.y + a.z * b.z + a.w * b.w;
}

__global__ __launch_bounds__(256)
void attn_kernel(const float* __restrict__ qkv, float* __restrict__ ctx,
                 float* __restrict__ wout) {
    int t = blockIdx.x * blockDim.x + threadIdx.x;   // b*8 + h
    int b = t >> 3;
    int h = t & 7;

    const float* base = qkv + (size_t)(2 * b) * QKVN + h * DH;
    const float* q0 = base;
    const float* q1 = base + QKVN;
    const float* k0 = base + 512;
    const float* k1 = base + 512 + QKVN;
    const float* v0 = base + 1024;
    const float* v1 = base + 1024 + QKVN;

    float s00 = 0.f, s01 = 0.f, s10 = 0.f, s11 = 0.f;
#pragma unroll
    for (int d = 0; d < DH; d += 4) {
        float4 qa = *(const float4*)(q0 + d);
        float4 qb = *(const float4*)(q1 + d);
        float4 ka = *(const float4*)(k0 + d);
        float4 kb = *(const float4*)(k1 + d);
        s00 += dot4(qa, ka); s01 += dot4(qa, kb);
        s10 += dot4(qb, ka); s11 += dot4(qb, kb);
    }
    const float sc = 0.125f;   // 1/sqrt(64)
    s00 *= sc; s01 *= sc; s10 *= sc; s11 *= sc;

    float m0 = fmaxf(s00, s01);
    float e00 = expf(s00 - m0), e01 = expf(s01 - m0);
    float r0 = 1.0f / (e00 + e01);
    float a00 = e00 * r0, a01 = e01 * r0;

    float m1 = fmaxf(s10, s11);
    float e10 = expf(s10 - m1), e11 = expf(s11 - m1);
    float r1 = 1.0f / (e10 + e11);
    float a10 = e10 * r1, a11 = e11 * r1;

    float* c0 = ctx + (size_t)(2 * b) * EDIM + h * DH;
    float* c1 = c0 + EDIM;
#pragma unroll
    for (int d = 0; d < DH; d += 4) {
        float4 va = *(const float4*)(v0 + d);
        float4 vb = *(const float4*)(v1 + d);
        float4 o0, o1;
        o0.x = a00 * va.x + a01 * vb.x;  o0.y = a00 * va.y + a01 * vb.y;
        o0.z = a00 * va.z + a01 * vb.z;  o0.w = a00 * va.w + a01 * vb.w;
        o1.x = a10 * va.x + a11 * vb.x;  o1.y = a10 * va.y + a11 * vb.y;
        o1.z = a10 * va.z + a11 * vb.z;  o1.w = a10 * va.w + a11 * vb.w;
        *(float4*)(c0 + d) = o0;
        *(float4*)(c1 + d) = o1;
    }

    // mean over heads: lanes of same b are 8 consecutive lanes in a warp
    float w0 = a00, w1 = a01, w2 = a10, w3 = a11;
#pragma unroll
    for (int off = 4; off >= 1; off >>= 1) {
        w0 += __shfl_xor_sync(0xffffffffu, w0, off);
        w1 += __shfl_xor_sync(0xffffffffu, w1, off);
        w2 += __shfl_xor_sync(0xffffffffu, w2, off);
        w3 += __shfl_xor_sync(0xffffffffu, w3, off);
    }
    if (h == 0) {
        float4 w;
        w.x = w0 * 0.125f; w.y = w1 * 0.125f; w.z = w2 * 0.125f; w.w = w3 * 0.125f;
        *(float4*)(wout + (size_t)b * 4) = w;
    }
}

// ---------------- layernorm over 256, one block per row ----------------
__global__ __launch_bounds__(256)
void ln_kernel(const float* __restrict__ o, const float* __restrict__ gamma,
               const float* __restrict__ beta, float* __restrict__ out) {
    __shared__ float s1[256];
    __shared__ float s2[256];
    int b = blockIdx.x;
    int j = threadIdx.x;
    float v = o[(size_t)b * OUTD + j];
    s1[j] = v;
    s2[j] = v * v;
    __syncthreads();
#pragma unroll
    for (int st = 128; st > 0; st >>= 1) {
        if (j < st) { s1[j] += s1[j + st]; s2[j] += s2[j + st]; }
        __syncthreads();
    }
    float mu  = s1[0] * (1.0f / OUTD);
    float var = s2[0] * (1.0f / OUTD) - mu * mu;
    float inv = rsqrtf(var + 1e-5f);
    out[(size_t)b * OUTD + j] = (v - mu) * inv * gamma[j] + beta[j];
}

// ---------------- launch ----------------
extern "C" void kernel_launch(void* const* d_in, const int* in_sizes, int n_in,
                              void* d_out, int out_size) {
    const float* vis  = (const float*)d_in[0];
    const float* txt  = (const float*)d_in[1];
    const float* wqkv = (const float*)d_in[2];
    const float* bqkv = (const float*)d_in[3];
    const float* wo   = (const float*)d_in[4];
    const float* bo   = (const float*)d_in[5];
    const float* w1   = (const float*)d_in[6];
    const float* b1   = (const float*)d_in[7];
    const float* w2   = (const float*)d_in[8];
    const float* b2   = (const float*)d_in[9];
    const float* gam  = (const float*)d_in[10];
    const float* bet  = (const float*)d_in[11];

    float* out     = (float*)d_out;
    float* fused   = out;                               // B x 256
    float* weights = out + (size_t)BATCH * OUTD;        // B x 4

    float *p_qkv, *p_ctx, *p_att, *p_h, *p_o;
    cudaGetSymbolAddress((void**)&p_qkv, g_qkv);
    cudaGetSymbolAddress((void**)&p_ctx, g_ctx);
    cudaGetSymbolAddress((void**)&p_att, g_att);
    cudaGetSymbolAddress((void**)&p_h,   g_h);
    cudaGetSymbolAddress((void**)&p_o,   g_o);

    // 1) QKV = X @ Wqkv^T + b        (2B x 1536)
    sgemm_qkv<<<dim3(QKVN / 128, ROWS2 / 128), 256>>>(vis, txt, wqkv, bqkv, p_qkv);

    // 2) attention -> ctx (2B x 512) + weights (B x 4)
    attn_kernel<<<(BATCH * NH) / 256, 256>>>(p_qkv, p_ctx, weights);

    // 3) ATT = CTX @ Wout^T + b      (2B x 512)
    sgemm_nt<0><<<dim3(EDIM / 128, ROWS2 / 128), 256>>>(p_ctx, wo, bo, p_att, ROWS2, EDIM, EDIM);

    // 4) H = gelu(ATT.view(B,1024) @ W1^T + b1)   (B x 512)
    sgemm_nt<1><<<dim3(HIDD / 128, BATCH / 128), 256>>>(p_att, w1, b1, p_h, BATCH, HIDD, CONCATD);

    // 5) O = H @ W2^T + b2           (B x 256)
    sgemm_nt<0><<<dim3(OUTD / 128, BATCH / 128), 256>>>(p_h, w2, b2, p_o, BATCH, OUTD, HIDD);

    // 6) layernorm -> fused
    ln_kernel<<<BATCH, 256>>>(p_o, gam, bet, fused);
}

// round 3
// speedup vs baseline: 2.2216x; 2.2216x over previous
#include <cuda_runtime.h>
#include <math.h>
#include <stdint.h>

// ---------------- problem dims ----------------
#define BATCH   65536
#define EDIM    512
#define NH      8
#define DH      64
#define ROWS2   (2*BATCH)      // 131072 sequence rows
#define QKVN    1536
#define CONCATD 1024
#define HIDD    512
#define OUTD    256

// ---------------- scratch (no allocations allowed) ----------------
__device__ float g_qkv[(size_t)ROWS2 * QKVN];   // 2B x 1536
__device__ float g_ctx[(size_t)ROWS2 * EDIM];   // 2B x 512
__device__ float g_att[(size_t)ROWS2 * EDIM];   // 2B x 512  (== B x 1024 view)
__device__ float g_h  [(size_t)BATCH * HIDD];   // B x 512
__device__ float g_o  [(size_t)BATCH * OUTD];   // B x 256

// ---------------- PTX helpers ----------------
__device__ __forceinline__ uint32_t smem_u32(const void* p) {
    uint32_t a;
    asm("{ .reg .u64 t; cvta.to.shared.u64 t, %1; cvt.u32.u64 %0, t; }" : "=r"(a) : "l"(p));
    return a;
}
__device__ __forceinline__ void cp16(uint32_t dst, const void* src) {
    asm volatile("cp.async.cg.shared.global [%0], [%1], 16;" :: "r"(dst), "l"(src));
}
#define CP_COMMIT() asm volatile("cp.async.commit_group;" ::: "memory")
#define CP_WAIT(n)  asm volatile("cp.async.wait_group %0;" :: "n"(n) : "memory")

__device__ __forceinline__ uint32_t f2tf32(float v) {
    uint32_t r;
    asm("cvt.rna.tf32.f32 %0, %1;" : "=r"(r) : "f"(v));
    return r;
}

// D += A*B  (m16n8k8, tf32 in, f32 out)
__device__ __forceinline__ void mma_tf32(float* d, const uint32_t* a, const uint32_t* b) {
    asm volatile(
        "mma.sync.aligned.m16n8k8.row.col.f32.tf32.tf32.f32 "
        "{%0,%1,%2,%3}, {%4,%5,%6,%7}, {%8,%9}, {%0,%1,%2,%3};"
        : "+f"(d[0]), "+f"(d[1]), "+f"(d[2]), "+f"(d[3])
        : "r"(a[0]), "r"(a[1]), "r"(a[2]), "r"(a[3]), "r"(b[0]), "r"(b[1]));
}

// ---------------- tf32 mma.sync GEMM ----------------
// C[M,N] = A[M,K] @ W[N,K]^T + bias (+optional exact GELU)
// CTA 128x128x32, 2-stage cp.async, 8 warps (2x4), warp tile 64x32.
#define PADK 36                       // 32 + 4 floats per smem row
#define TILE_FLOATS (128 * PADK)      // per operand per stage
#define STAGE_FLOATS (2 * TILE_FLOATS)
#define SMEM_BYTES (2 * STAGE_FLOATS * 4)   // 73728

template <int INTERLEAVE, int EPI>
__global__ __launch_bounds__(256, 2)
void tc_gemm(const float* __restrict__ A0, const float* __restrict__ A1,
             const float* __restrict__ W, const float* __restrict__ bias,
             float* __restrict__ C, int M, int N, int K) {
    extern __shared__ float smem[];
    // stage s: A at smem + s*STAGE_FLOATS, B at +TILE_FLOATS
    const uint32_t smem_u = smem_u32(smem);

    const int tid = threadIdx.x;
    const int wid = tid >> 5;
    const int lane = tid & 31;
    const int g  = lane >> 2;      // 0..7
    const int t4 = lane & 3;       // 0..3
    const int wm = (wid >> 2) * 64;   // warp row base within tile
    const int wn = (wid & 3) * 32;    // warp col base within tile
    const int m0 = blockIdx.y * 128;
    const int n0 = blockIdx.x * 128;

    // global load geometry: thread t loads row t>>1, half (t&1): 4 float4
    const int lrow = tid >> 1;
    const int lhalf = (tid & 1) * 4;   // float4 index base within row
    const float* aPtr;
    if (INTERLEAVE) {
        int grow = m0 + lrow;
        aPtr = ((grow & 1) ? A1 : A0) + (size_t)(grow >> 1) * K + lhalf * 4;
    } else {
        aPtr = A0 + (size_t)(m0 + lrow) * K + lhalf * 4;
    }
    const float* bPtr = W + (size_t)(n0 + lrow) * K + lhalf * 4;
    const uint32_t aDst = smem_u + (lrow * PADK + lhalf * 4) * 4;
    const uint32_t bDst = aDst + TILE_FLOATS * 4;

    float acc[4][4][4];
#pragma unroll
    for (int i = 0; i < 4; i++)
#pragma unroll
        for (int j = 0; j < 4; j++)
#pragma unroll
            for (int r = 0; r < 4; r++) acc[i][j][r] = 0.f;

    const int KT = K >> 5;

    // prologue: stage 0
#pragma unroll
    for (int i = 0; i < 4; i++) cp16(aDst + i * 16, aPtr + i * 4);
#pragma unroll
    for (int i = 0; i < 4; i++) cp16(bDst + i * 16, bPtr + i * 4);
    CP_COMMIT();

    // warp-local smem base offsets (in floats)
    const float* As;
    const float* Bs;

    for (int kt = 0; kt < KT; kt++) {
        const int s = kt & 1;
        if (kt + 1 < KT) {
            const int sn = s ^ 1;
            const uint32_t aD = aDst + sn * (STAGE_FLOATS * 4);
            const uint32_t bD = bDst + sn * (STAGE_FLOATS * 4);
            const float* ap = aPtr + (kt + 1) * 32;
            const float* bp = bPtr + (kt + 1) * 32;
#pragma unroll
            for (int i = 0; i < 4; i++) cp16(aD + i * 16, ap + i * 4);
#pragma unroll
            for (int i = 0; i < 4; i++) cp16(bD + i * 16, bp + i * 4);
            CP_COMMIT();
            CP_WAIT(1);
        } else {
            CP_WAIT(0);
        }
        __syncthreads();

        As = smem + s * STAGE_FLOATS;
        Bs = As + TILE_FLOATS;

#pragma unroll
        for (int kk = 0; kk < 4; kk++) {
            const int k8 = kk * 8;
            uint32_t af[4][4], bf[4][2];
#pragma unroll
            for (int mt = 0; mt < 4; mt++) {
                const float* r0 = As + (wm + mt * 16 + g) * PADK + k8;
                const float* r1 = r0 + 8 * PADK;
                af[mt][0] = f2tf32(r0[t4]);
                af[mt][1] = f2tf32(r1[t4]);
                af[mt][2] = f2tf32(r0[t4 + 4]);
                af[mt][3] = f2tf32(r1[t4 + 4]);
            }
#pragma unroll
            for (int nt = 0; nt < 4; nt++) {
                const float* rn = Bs + (wn + nt * 8 + g) * PADK + k8;
                bf[nt][0] = f2tf32(rn[t4]);
                bf[nt][1] = f2tf32(rn[t4 + 4]);
            }
#pragma unroll
            for (int mt = 0; mt < 4; mt++)
#pragma unroll
                for (int nt = 0; nt < 4; nt++)
                    mma_tf32(acc[mt][nt], af[mt], bf[nt]);
        }
        __syncthreads();
    }

    // epilogue
#pragma unroll
    for (int mt = 0; mt < 4; mt++) {
        const size_t r0 = (size_t)(m0 + wm + mt * 16 + g);
        const size_t r1 = r0 + 8;
#pragma unroll
        for (int nt = 0; nt < 4; nt++) {
            const int col = n0 + wn + nt * 8 + t4 * 2;
            const float b0 = __ldg(bias + col);
            const float b1 = __ldg(bias + col + 1);
            float2 v0, v1;
            v0.x = acc[mt][nt][0] + b0;  v0.y = acc[mt][nt][1] + b1;
            v1.x = acc[mt][nt][2] + b0;  v1.y = acc[mt][nt][3] + b1;
            if (EPI == 1) {
                v0.x = 0.5f * v0.x * (1.0f + erff(v0.x * 0.70710678118654752f));
                v0.y = 0.5f * v0.y * (1.0f + erff(v0.y * 0.70710678118654752f));
                v1.x = 0.5f * v1.x * (1.0f + erff(v1.x * 0.70710678118654752f));
                v1.y = 0.5f * v1.y * (1.0f + erff(v1.y * 0.70710678118654752f));
            }
            *(float2*)(C + r0 * N + col) = v0;
            *(float2*)(C + r1 * N + col) = v1;
        }
    }
}

// ---------------- attention: one thread per (b, h); seq len 2 ----------------
__device__ __forceinline__ float dot4(float4 a, float4 b) {
    return a.x * b.x + a.y * b.y + a.z * b.z + a.w * b.w;
}

__global__ __launch_bounds__(256)
void attn_kernel(const float* __restrict__ qkv, float* __restrict__ ctx,
                 float* __restrict__ wout) {
    int t = blockIdx.x * blockDim.x + threadIdx.x;   // b*8 + h
    int b = t >> 3;
    int h = t & 7;

    const float* base = qkv + (size_t)(2 * b) * QKVN + h * DH;
    const float* q0 = base;
    const float* q1 = base + QKVN;
    const float* k0 = base + 512;
    const float* k1 = base + 512 + QKVN;
    const float* v0 = base + 1024;
    const float* v1 = base + 1024 + QKVN;

    float s00 = 0.f, s01 = 0.f, s10 = 0.f, s11 = 0.f;
#pragma unroll
    for (int d = 0; d < DH; d += 4) {
        float4 qa = *(const float4*)(q0 + d);
        float4 qb = *(const float4*)(q1 + d);
        float4 ka = *(const float4*)(k0 + d);
        float4 kb = *(const float4*)(k1 + d);
        s00 += dot4(qa, ka); s01 += dot4(qa, kb);
        s10 += dot4(qb, ka); s11 += dot4(qb, kb);
    }
    const float sc = 0.125f;   // 1/sqrt(64)
    s00 *= sc; s01 *= sc; s10 *= sc; s11 *= sc;

    float m0 = fmaxf(s00, s01);
    float e00 = expf(s00 - m0), e01 = expf(s01 - m0);
    float r0 = 1.0f / (e00 + e01);
    float a00 = e00 * r0, a01 = e01 * r0;

    float m1 = fmaxf(s10, s11);
    float e10 = expf(s10 - m1), e11 = expf(s11 - m1);
    float r1 = 1.0f / (e10 + e11);
    float a10 = e10 * r1, a11 = e11 * r1;

    float* c0 = ctx + (size_t)(2 * b) * EDIM + h * DH;
    float* c1 = c0 + EDIM;
#pragma unroll
    for (int d = 0; d < DH; d += 4) {
        float4 va = *(const float4*)(v0 + d);
        float4 vb = *(const float4*)(v1 + d);
        float4 o0, o1;
        o0.x = a00 * va.x + a01 * vb.x;  o0.y = a00 * va.y + a01 * vb.y;
        o0.z = a00 * va.z + a01 * vb.z;  o0.w = a00 * va.w + a01 * vb.w;
        o1.x = a10 * va.x + a11 * vb.x;  o1.y = a10 * va.y + a11 * vb.y;
        o1.z = a10 * va.z + a11 * vb.z;  o1.w = a10 * va.w + a11 * vb.w;
        *(float4*)(c0 + d) = o0;
        *(float4*)(c1 + d) = o1;
    }

    // mean over heads: 8 consecutive lanes share a b
    float w0 = a00, w1 = a01, w2 = a10, w3 = a11;
#pragma unroll
    for (int off = 4; off >= 1; off >>= 1) {
        w0 += __shfl_xor_sync(0xffffffffu, w0, off);
        w1 += __shfl_xor_sync(0xffffffffu, w1, off);
        w2 += __shfl_xor_sync(0xffffffffu, w2, off);
        w3 += __shfl_xor_sync(0xffffffffu, w3, off);
    }
    if (h == 0) {
        float4 w;
        w.x = w0 * 0.125f; w.y = w1 * 0.125f; w.z = w2 * 0.125f; w.w = w3 * 0.125f;
        *(float4*)(wout + (size_t)b * 4) = w;
    }
}

// ---------------- layernorm over 256, one block per row ----------------
__global__ __launch_bounds__(256)
void ln_kernel(const float* __restrict__ o, const float* __restrict__ gamma,
               const float* __restrict__ beta, float* __restrict__ out) {
    __shared__ float s1[256];
    __shared__ float s2[256];
    int b = blockIdx.x;
    int j = threadIdx.x;
    float v = o[(size_t)b * OUTD + j];
    s1[j] = v;
    s2[j] = v * v;
    __syncthreads();
#pragma unroll
    for (int st = 128; st > 0; st >>= 1) {
        if (j < st) { s1[j] += s1[j + st]; s2[j] += s2[j + st]; }
        __syncthreads();
    }
    float mu  = s1[0] * (1.0f / OUTD);
    float var = s2[0] * (1.0f / OUTD) - mu * mu;
    float inv = rsqrtf(var + 1e-5f);
    out[(size_t)b * OUTD + j] = (v - mu) * inv * gamma[j] + beta[j];
}

// ---------------- launch ----------------
extern "C" void kernel_launch(void* const* d_in, const int* in_sizes, int n_in,
                              void* d_out, int out_size) {
    const float* vis  = (const float*)d_in[0];
    const float* txt  = (const float*)d_in[1];
    const float* wqkv = (const float*)d_in[2];
    const float* bqkv = (const float*)d_in[3];
    const float* wo   = (const float*)d_in[4];
    const float* bo   = (const float*)d_in[5];
    const float* w1   = (const float*)d_in[6];
    const float* b1   = (const float*)d_in[7];
    const float* w2   = (const float*)d_in[8];
    const float* b2   = (const float*)d_in[9];
    const float* gam  = (const float*)d_in[10];
    const float* bet  = (const float*)d_in[11];

    float* out     = (float*)d_out;
    float* fused   = out;                               // B x 256
    float* weights = out + (size_t)BATCH * OUTD;        // B x 4

    float *p_qkv, *p_ctx, *p_att, *p_h, *p_o;
    cudaGetSymbolAddress((void**)&p_qkv, g_qkv);
    cudaGetSymbolAddress((void**)&p_ctx, g_ctx);
    cudaGetSymbolAddress((void**)&p_att, g_att);
    cudaGetSymbolAddress((void**)&p_h,   g_h);
    cudaGetSymbolAddress((void**)&p_o,   g_o);

    cudaFuncSetAttribute(tc_gemm<1,0>, cudaFuncAttributeMaxDynamicSharedMemorySize, SMEM_BYTES);
    cudaFuncSetAttribute(tc_gemm<0,0>, cudaFuncAttributeMaxDynamicSharedMemorySize, SMEM_BYTES);
    cudaFuncSetAttribute(tc_gemm<0,1>, cudaFuncAttributeMaxDynamicSharedMemorySize, SMEM_BYTES);

    // 1) QKV = X @ Wqkv^T + b        (2B x 1536)
    tc_gemm<1,0><<<dim3(QKVN / 128, ROWS2 / 128), 256, SMEM_BYTES>>>(
        vis, txt, wqkv, bqkv, p_qkv, ROWS2, QKVN, EDIM);

    // 2) attention -> ctx (2B x 512) + weights (B x 4)
    attn_kernel<<<(BATCH * NH) / 256, 256>>>(p_qkv, p_ctx, weights);

    // 3) ATT = CTX @ Wout^T + b      (2B x 512)
    tc_gemm<0,0><<<dim3(EDIM / 128, ROWS2 / 128), 256, SMEM_BYTES>>>(
        p_ctx, nullptr, wo, bo, p_att, ROWS2, EDIM, EDIM);

    // 4) H = gelu(ATT.view(B,1024) @ W1^T + b1)   (B x 512)
    tc_gemm<0,1><<<dim3(HIDD / 128, BATCH / 128), 256, SMEM_BYTES>>>(
        p_att, nullptr, w1, b1, p_h, BATCH, HIDD, CONCATD);

    // 5) O = H @ W2^T + b2           (B x 256)
    tc_gemm<0,0><<<dim3(OUTD / 128, BATCH / 128), 256, SMEM_BYTES>>>(
        p_h, nullptr, w2, b2, p_o, BATCH, OUTD, HIDD);

    // 6) layernorm -> fused
    ln_kernel<<<BATCH, 256>>>(p_o, gam, bet, fused);
}